// round 17
// baseline (speedup 1.0000x reference)
#include <cuda_runtime.h>
#include <cuda_bf16.h>
#include <math.h>
#include <stdint.h>

// Problem constants (fixed shapes from reference)
#define NQ    16384
#define NK    7933
#define NKP   7936
#define D_IN  1024
#define HD    512
#define THRE_IDX 11469   // NQ - int(0.3*NQ)

// ---------------------------------------------------------------------------
// Scratch (device globals)
// ---------------------------------------------------------------------------
__device__ __align__(16) float g_qt[NQ * HD];   // tanh(query @ wq^T)
__device__ __align__(16) float g_kt[NK * HD];   // tanh(key_x @ wk^T)
__device__ float g_qn2p[4 * NQ];     // row-norm partials (slot-major, 4 slots)
__device__ float g_kn2p[4 * NKP];
__device__ __align__(16) float g_v[HD];
__device__ float g_A1[NQ];
__device__ float g_thre;
__device__ float g_m;
__device__ float g_Z;
__device__ float g_z[HD];

// pre-split bf16 hi/lo weights (4 MB total; L2-resident)
__device__ __align__(16) __nv_bfloat16 g_wqh[HD * D_IN];
__device__ __align__(16) __nv_bfloat16 g_wql[HD * D_IN];
__device__ __align__(16) __nv_bfloat16 g_wkh[HD * D_IN];
__device__ __align__(16) __nv_bfloat16 g_wkl[HD * D_IN];

// ---------------------------------------------------------------------------
__global__ void init_kernel() {           // 1 block, 512 threads
    int t = threadIdx.x;
    g_v[t] = 0.f;
    g_z[t] = 0.f;
}

__device__ __forceinline__ void split4(float4 v, uint2& h, uint2& l) {
    __nv_bfloat162 h01 = __floats2bfloat162_rn(v.x, v.y);
    __nv_bfloat162 h23 = __floats2bfloat162_rn(v.z, v.w);
    __nv_bfloat162 l01 = __floats2bfloat162_rn(v.x - __bfloat162float(h01.x),
                                               v.y - __bfloat162float(h01.y));
    __nv_bfloat162 l23 = __floats2bfloat162_rn(v.z - __bfloat162float(h23.x),
                                               v.w - __bfloat162float(h23.y));
    h = make_uint2(*(uint32_t*)&h01, *(uint32_t*)&h23);
    l = make_uint2(*(uint32_t*)&l01, *(uint32_t*)&l23);
}

#define W4 (HD * D_IN / 4)    // 131072 float4 granules per weight matrix

__global__ void wconv_kernel(const float* __restrict__ wq_w,
                             const float* __restrict__ wk_w) {
    int i = blockIdx.x * 256 + threadIdx.x;      // 0 .. 2*W4-1
    bool isq = (i < W4);
    int idx = isq ? i : i - W4;
    const float4* src = isq ? (const float4*)wq_w : (const float4*)wk_w;
    uint2 h, l;
    split4(src[idx], h, l);
    (isq ? (uint2*)g_wqh : (uint2*)g_wkh)[idx] = h;
    (isq ? (uint2*)g_wql : (uint2*)g_wkl)[idx] = l;
}

// ---------------------------------------------------------------------------
// mma.sync bf16 GEMM + tanh + row-norm partial stores.
// M-tile 64 x N-tile 512 (full HD), 512 threads (16 warps, warp tile 16x128).
// A: fp32 LDG + in-register hi/lo split (converted ONCE per tile).
// W: cp.async of pre-split bf16 hi/lo. Double-buffered; next-chunk issue is
// AFTER the barrier (fixes R14's smem WAR race).
// ---------------------------------------------------------------------------
__device__ __forceinline__ uint32_t smem_u32(const void* p) {
    uint32_t a;
    asm("{ .reg .u64 t; cvta.to.shared.u64 t, %1; cvt.u32.u64 %0, t; }" : "=r"(a) : "l"(p));
    return a;
}
__device__ __forceinline__ void ldm_x4(uint32_t* r, uint32_t addr) {
    asm volatile("ldmatrix.sync.aligned.m8n8.x4.shared.b16 {%0,%1,%2,%3}, [%4];"
                 : "=r"(r[0]), "=r"(r[1]), "=r"(r[2]), "=r"(r[3]) : "r"(addr));
}
__device__ __forceinline__ void mma_bf16(float* d, const uint32_t* a, const uint32_t* b) {
    asm volatile(
        "mma.sync.aligned.m16n8k16.row.col.f32.bf16.bf16.f32 "
        "{%0,%1,%2,%3}, {%4,%5,%6,%7}, {%8,%9}, {%0,%1,%2,%3};"
        : "+f"(d[0]), "+f"(d[1]), "+f"(d[2]), "+f"(d[3])
        : "r"(a[0]), "r"(a[1]), "r"(a[2]), "r"(a[3]), "r"(b[0]), "r"(b[1]));
}
__device__ __forceinline__ void cp16(uint32_t s, const void* g) {
    asm volatile("cp.async.cg.shared.global [%0], [%1], 16;" :: "r"(s), "l"(g));
}

#define LDS 40                     // bf16 stride per 32-wide row (+8 pad)
#define NCH (D_IN / 32)            // 32 K-chunks
#define AH_OFF 0                   // A hi: 64 rows * 80B = 5120
#define AL_OFF 5120                // A lo
#define WH_OFF 10240               // W hi: 512 rows * 80B = 40960
#define WL_OFF 51200               // W lo
#define BUF_BYTES 92160
#define GEMM_SMEM (2 * BUF_BYTES)  // 184320

__device__ __forceinline__ void issue_w(uint32_t sstage,
                                        const __nv_bfloat16* __restrict__ Wh,
                                        const __nv_bfloat16* __restrict__ Wl,
                                        int k0, int tid) {
#pragma unroll
    for (int j = 0; j < 4; j++) {
        int id = tid + j * 512;        // 0..2047
        int r = id >> 2, c8 = id & 3;
        uint32_t soff = (uint32_t)(r * 80 + c8 * 16);
        const size_t goff = (size_t)r * D_IN + k0 + c8 * 8;
        cp16(sstage + WH_OFF + soff, Wh + goff);
        cp16(sstage + WL_OFF + soff, Wl + goff);
    }
}

__global__ __launch_bounds__(512)
void gemm_tc_kernel(const float* __restrict__ query, const float* __restrict__ wq_b,
                    const float* __restrict__ key_x, const float* __restrict__ wk_b)
{
    extern __shared__ __align__(16) char sm[];
    const int tid = threadIdx.x;
    const int wid = tid >> 5;
    const int lane = tid & 31;
    const int by = blockIdx.x;

    const float* Ag; const __nv_bfloat16 *Wh, *Wl;
    const float* bias; float* C; float* N2P; int M, MP, bm;
    if (by < NQ / 64) {
        Ag = query; Wh = g_wqh; Wl = g_wql;
        bias = wq_b; C = g_qt; N2P = g_qn2p; M = NQ; MP = NQ; bm = by * 64;
    } else {
        Ag = key_x; Wh = g_wkh; Wl = g_wkl;
        bias = wk_b; C = g_kt; N2P = g_kn2p; M = NK; MP = NKP;
        bm = (by - NQ / 64) * 64;
    }

    const uint32_t smb = smem_u32(sm);
    const int warp_m = (wid & 3) * 16;      // 4 m-groups of 16
    const int warp_n = (wid >> 2) * 128;    // 4 n-groups of 128

    float acc[16][4];
#pragma unroll
    for (int nt = 0; nt < 16; nt++)
#pragma unroll
        for (int i = 0; i < 4; i++) acc[nt][i] = 0.f;

    // A staging: 1 float4 per thread (64 rows x 8 granules = 512)
    const int arow = tid >> 3, aq = tid & 7;
    const int agr = bm + arow;
    float4 ra = (agr < M) ? *(const float4*)(Ag + (size_t)agr * D_IN + aq * 4)
                          : make_float4(0.f, 0.f, 0.f, 0.f);
    issue_w(smb, Wh, Wl, 0, tid);
    asm volatile("cp.async.commit_group;");

    const uint32_t aboff = (uint32_t)(arow * LDS + aq * 4) * 2;

    for (int c = 0; c < NCH; c++) {
        const uint32_t base = smb + (c & 1) * BUF_BYTES;
        // convert + store A chunk c into buffer c&1
        {
            uint2 h, l;
            split4(ra, h, l);
            *(uint2*)(sm + (c & 1) * BUF_BYTES + AH_OFF + aboff) = h;
            *(uint2*)(sm + (c & 1) * BUF_BYTES + AL_OFF + aboff) = l;
        }
        asm volatile("cp.async.wait_group 0;");   // W chunk c landed
        __syncthreads();   // A visible; separates compute(c-1) from issue below

        if (c + 1 < NCH) {
            const int k0 = (c + 1) * 32;
            issue_w(smb + ((c + 1) & 1) * BUF_BYTES, Wh, Wl, k0, tid);
            asm volatile("cp.async.commit_group;");
            ra = (agr < M) ? *(const float4*)(Ag + (size_t)agr * D_IN + k0 + aq * 4)
                           : make_float4(0.f, 0.f, 0.f, 0.f);
        }

        // compute chunk c
#pragma unroll
        for (int kk = 0; kk < 2; kk++) {
            uint32_t ah[4], al[4];
            {
                int r = warp_m + (lane & 15);
                int cc = kk * 16 + (lane >> 4) * 8;
                uint32_t off = (uint32_t)(r * LDS + cc) * 2;
                ldm_x4(ah, base + AH_OFF + off);
                ldm_x4(al, base + AL_OFF + off);
            }
#pragma unroll
            for (int nt2 = 0; nt2 < 8; nt2++) {
                uint32_t bh[4], bl[4];
                int r = warp_n + nt2 * 16 + ((lane >> 4) ? 8 : 0) + (lane & 7);
                int cc = kk * 16 + ((lane >> 3) & 1) * 8;
                uint32_t off = (uint32_t)(r * LDS + cc) * 2;
                ldm_x4(bh, base + WH_OFF + off);
                ldm_x4(bl, base + WL_OFF + off);
#pragma unroll
                for (int hf = 0; hf < 2; hf++) {
                    int nt = nt2 * 2 + hf;
                    mma_bf16(acc[nt], ah, &bh[hf * 2]);
                    mma_bf16(acc[nt], ah, &bl[hf * 2]);
                    mma_bf16(acc[nt], al, &bh[hf * 2]);
                }
            }
        }
    }

    // ---- epilogue: bias + tanh + row-norm partial STG (4 slots) ----
    const int ng = wid >> 2;                 // n-group = partial slot
    float rs[2] = {0.f, 0.f};
    int r0 = bm + warp_m + (lane >> 2);
#pragma unroll
    for (int nt = 0; nt < 16; nt++) {
        int gc = warp_n + nt * 8 + (lane & 3) * 2;
        float b0 = bias[gc], b1 = bias[gc + 1];
        if (r0 < M) {
            float t0 = tanhf(acc[nt][0] + b0);
            float t1 = tanhf(acc[nt][1] + b1);
            C[(size_t)r0 * HD + gc]     = t0;
            C[(size_t)r0 * HD + gc + 1] = t1;
            rs[0] = fmaf(t0, t0, fmaf(t1, t1, rs[0]));
        }
        if (r0 + 8 < M) {
            float t2 = tanhf(acc[nt][2] + b0);
            float t3 = tanhf(acc[nt][3] + b1);
            C[(size_t)(r0 + 8) * HD + gc]     = t2;
            C[(size_t)(r0 + 8) * HD + gc + 1] = t3;
            rs[1] = fmaf(t2, t2, fmaf(t3, t3, rs[1]));
        }
    }
#pragma unroll
    for (int h = 0; h < 2; h++) {
        float v = rs[h];
        v += __shfl_xor_sync(0xffffffffu, v, 1);
        v += __shfl_xor_sync(0xffffffffu, v, 2);
        int row = bm + warp_m + (lane >> 2) + h * 8;
        if ((lane & 3) == 0 && row < M) N2P[ng * MP + row] = v;
    }
}

// ---------------------------------------------------------------------------
// Fused: s[k] = wa[k]/max(||kt_k||,eps);  v[h] += sum_k s[k]*kt[k][h]
// ---------------------------------------------------------------------------
__global__ __launch_bounds__(256)
void v_accum_kernel(const float* __restrict__ wa_w) {
    __shared__ float se[32];
    __shared__ float sv[256];
    const int tid = threadIdx.x;
    const int k0 = blockIdx.x * 32;
    const int cbase = blockIdx.y * 64;
    if (tid < 32) {
        int k = k0 + tid;
        float s = 0.f;
        if (k < NK) {
            float n2 = 0.f;
#pragma unroll
            for (int p = 0; p < 4; p++) n2 += g_kn2p[p * NKP + k];
            s = wa_w[k] / fmaxf(sqrtf(n2), 1e-12f);
        }
        se[tid] = s;
    }
    sv[tid] = 0.f;
    __syncthreads();

    const int c4   = cbase + (tid & 63);
    const int rowg = tid >> 6;
    const int r0   = rowg * 8;
    float4 a0 = make_float4(0.f,0.f,0.f,0.f), a1 = a0, a2 = a0, a3 = a0;
#pragma unroll
    for (int i = 0; i < 8; i += 4) {
        int kA = k0 + r0 + i;
        int kB = kA + 1, kC = kA + 2, kD = kA + 3;
        float sA = se[r0 + i],     sB = se[r0 + i + 1];
        float sC = se[r0 + i + 2], sD = se[r0 + i + 3];
        kA = min(kA, NK - 1); kB = min(kB, NK - 1);
        kC = min(kC, NK - 1); kD = min(kD, NK - 1);
        float4 vA = *(const float4*)(g_kt + (size_t)kA * HD + c4 * 4);
        float4 vB = *(const float4*)(g_kt + (size_t)kB * HD + c4 * 4);
        float4 vC = *(const float4*)(g_kt + (size_t)kC * HD + c4 * 4);
        float4 vD = *(const float4*)(g_kt + (size_t)kD * HD + c4 * 4);
        a0.x = fmaf(sA, vA.x, a0.x); a0.y = fmaf(sA, vA.y, a0.y);
        a0.z = fmaf(sA, vA.z, a0.z); a0.w = fmaf(sA, vA.w, a0.w);
        a1.x = fmaf(sB, vB.x, a1.x); a1.y = fmaf(sB, vB.y, a1.y);
        a1.z = fmaf(sB, vB.z, a1.z); a1.w = fmaf(sB, vB.w, a1.w);
        a2.x = fmaf(sC, vC.x, a2.x); a2.y = fmaf(sC, vC.y, a2.y);
        a2.z = fmaf(sC, vC.z, a2.z); a2.w = fmaf(sC, vC.w, a2.w);
        a3.x = fmaf(sD, vD.x, a3.x); a3.y = fmaf(sD, vD.y, a3.y);
        a3.z = fmaf(sD, vD.z, a3.z); a3.w = fmaf(sD, vD.w, a3.w);
    }
    int lc = (tid & 63) * 4;
    atomicAdd(&sv[lc + 0], a0.x + a1.x + a2.x + a3.x);
    atomicAdd(&sv[lc + 1], a0.y + a1.y + a2.y + a3.y);
    atomicAdd(&sv[lc + 2], a0.z + a1.z + a2.z + a3.z);
    atomicAdd(&sv[lc + 3], a0.w + a1.w + a2.w + a3.w);
    __syncthreads();
    atomicAdd(&g_v[cbase * 4 + tid], sv[tid]);
}

// A1[q] = dot(qt_q, v)/max(sqrt(qn2[q]),eps) + wa_b  — 4 rows per warp
__global__ void a1_kernel(const float* __restrict__ wa_b) {
    int w    = threadIdx.x >> 5;
    int lane = threadIdx.x & 31;
    int row0 = blockIdx.x * 32 + w * 4;
    const float4* q0 = (const float4*)(g_qt + (size_t)row0 * HD);
    const float4* q1 = (const float4*)(g_qt + (size_t)(row0 + 1) * HD);
    const float4* q2 = (const float4*)(g_qt + (size_t)(row0 + 2) * HD);
    const float4* q3 = (const float4*)(g_qt + (size_t)(row0 + 3) * HD);
    const float4* vv = (const float4*)g_v;
    float d0 = 0.f, d1 = 0.f, d2 = 0.f, d3 = 0.f;
#pragma unroll
    for (int j = 0; j < 4; j++) {
        float4 b = vv[lane + 32 * j];
        float4 a = q0[lane + 32 * j];
        float4 c = q1[lane + 32 * j];
        float4 e = q2[lane + 32 * j];
        float4 f = q3[lane + 32 * j];
        d0 = fmaf(a.x, b.x, fmaf(a.y, b.y, fmaf(a.z, b.z, fmaf(a.w, b.w, d0))));
        d1 = fmaf(c.x, b.x, fmaf(c.y, b.y, fmaf(c.z, b.z, fmaf(c.w, b.w, d1))));
        d2 = fmaf(e.x, b.x, fmaf(e.y, b.y, fmaf(e.z, b.z, fmaf(e.w, b.w, d2))));
        d3 = fmaf(f.x, b.x, fmaf(f.y, b.y, fmaf(f.z, b.z, fmaf(f.w, b.w, d3))));
    }
#pragma unroll
    for (int o = 16; o > 0; o >>= 1) {
        d0 += __shfl_xor_sync(0xffffffffu, d0, o);
        d1 += __shfl_xor_sync(0xffffffffu, d1, o);
        d2 += __shfl_xor_sync(0xffffffffu, d2, o);
        d3 += __shfl_xor_sync(0xffffffffu, d3, o);
    }
    if (lane == 0) {
        float wb = wa_b[0];
        float dd[4] = {d0, d1, d2, d3};
#pragma unroll
        for (int r = 0; r < 4; r++) {
            int row = row0 + r;
            float n2 = 0.f;
#pragma unroll
            for (int p = 0; p < 4; p++) n2 += g_qn2p[p * NQ + row];
            g_A1[row] = dd[r] / fmaxf(sqrtf(n2), 1e-12f) + wb;
        }
    }
}

// ---------------------------------------------------------------------------
// Exact k-th order statistic via 3-level radix select + global max + Z.
// ---------------------------------------------------------------------------
__device__ __forceinline__ uint32_t f2ord(float f) {
    uint32_t u = __float_as_uint(f);
    return u ^ ((u >> 31) ? 0xFFFFFFFFu : 0x80000000u);
}
__device__ __forceinline__ float ord2f(uint32_t u) {
    u ^= ((u >> 31) ? 0x80000000u : 0xFFFFFFFFu);
    return __uint_as_float(u);
}

__global__ void select_kernel() {
    __shared__ uint32_t hist[2048];
    __shared__ uint32_t wred[32];
    __shared__ uint32_t s_bin, s_base;
    __shared__ float s_max;
    __shared__ float fred[32];
    const int t = threadIdx.x;
    const int lane = t & 31, w = t >> 5;

    float mx = -INFINITY;
    for (int i = t; i < NQ; i += 1024) mx = fmaxf(mx, g_A1[i]);
#pragma unroll
    for (int o = 16; o > 0; o >>= 1) mx = fmaxf(mx, __shfl_xor_sync(0xffffffffu, mx, o));
    if (lane == 0) wred[w] = __float_as_uint(mx);
    __syncthreads();
    if (w == 0) {
        float m = __uint_as_float(wred[lane]);
#pragma unroll
        for (int o = 16; o > 0; o >>= 1) m = fmaxf(m, __shfl_xor_sync(0xffffffffu, m, o));
        if (lane == 0) s_max = m;
    }
    __syncthreads();

    uint32_t k = THRE_IDX;
    uint32_t prefix = 0, pmask = 0;
    const int shifts[3] = {21, 10, 0};
    const uint32_t widths[3] = {2048, 2048, 1024};

    for (int lev = 0; lev < 3; lev++) {
        const int sh = shifts[lev];
        const uint32_t width = widths[lev];
        const uint32_t bmask = width - 1;
        hist[t] = 0; hist[t + 1024] = 0;
        __syncthreads();
        for (int i = t; i < NQ; i += 1024) {
            uint32_t key = f2ord(g_A1[i]);
            if ((key & pmask) == prefix)
                atomicAdd(&hist[(key >> sh) & bmask], 1u);
        }
        __syncthreads();
        uint32_t c0 = (2u * t     < width) ? hist[2 * t]     : 0u;
        uint32_t c1 = (2u * t + 1 < width) ? hist[2 * t + 1] : 0u;
        uint32_t tsum = c0 + c1;
        uint32_t inc = tsum;
#pragma unroll
        for (int o = 1; o < 32; o <<= 1) {
            uint32_t v = __shfl_up_sync(0xffffffffu, inc, o);
            if (lane >= o) inc += v;
        }
        if (lane == 31) wred[w] = inc;
        __syncthreads();
        if (w == 0) {
            uint32_t v = wred[lane];
            uint32_t winc = v;
#pragma unroll
            for (int o = 1; o < 32; o <<= 1) {
                uint32_t x = __shfl_up_sync(0xffffffffu, winc, o);
                if (lane >= o) winc += x;
            }
            wred[lane] = winc - v;   // exclusive
        }
        __syncthreads();
        uint32_t ex = wred[w] + (inc - tsum);
        if (k >= ex && k < ex + c0)             { s_bin = 2 * t;     s_base = ex; }
        else if (k >= ex + c0 && k < ex + tsum) { s_bin = 2 * t + 1; s_base = ex + c0; }
        __syncthreads();
        uint32_t bin = s_bin;
        k -= s_base;
        prefix |= (bin << sh);
        pmask  |= (bmask << sh);
        __syncthreads();
    }

    const float thre = ord2f(prefix);
    const float m = fmaxf(s_max, 0.f);

    float zs = 0.f;
    for (int i = t; i < NQ; i += 1024) {
        float a = g_A1[i];
        float tt = (a > thre) ? a : 0.f;
        zs += expf(tt - m);
    }
#pragma unroll
    for (int o = 16; o > 0; o >>= 1) zs += __shfl_xor_sync(0xffffffffu, zs, o);
    if (lane == 0) fred[w] = zs;
    __syncthreads();
    if (w == 0) {
        float s = fred[lane];
#pragma unroll
        for (int o = 16; o > 0; o >>= 1) s += __shfl_xor_sync(0xffffffffu, s, o);
        if (lane == 0) {
            g_thre = thre;
            g_m = m;
            g_Z = s;
        }
    }
}

// ---------------------------------------------------------------------------
// Fused: e = exp(thresholded(A1)-m); out[1+q] = e/Z; z[h] += sum_q e_q*qt[q][h]
// ---------------------------------------------------------------------------
__global__ __launch_bounds__(256)
void e_accum_kernel(float* __restrict__ out) {
    __shared__ float se[32];
    __shared__ float sz[256];
    const int tid = threadIdx.x;
    const int q0 = blockIdx.x * 32;
    const int cbase = blockIdx.y * 64;
    if (tid < 32) {
        int q = q0 + tid;
        float a = g_A1[q];
        float tt = (a > g_thre) ? a : 0.f;
        float e = expf(tt - g_m);
        se[tid] = e;
        if (blockIdx.y == 0) out[1 + q] = e / g_Z;
    }
    sz[tid] = 0.f;
    __syncthreads();

    const int c4   = cbase + (tid & 63);
    const int rowg = tid >> 6;
    const int r0   = rowg * 8;
    float4 a0 = make_float4(0.f,0.f,0.f,0.f), a1 = a0, a2 = a0, a3 = a0;
#pragma unroll
    for (int i = 0; i < 8; i += 4) {
        int qA = q0 + r0 + i;
        float sA = se[r0 + i],     sB = se[r0 + i + 1];
        float sC = se[r0 + i + 2], sD = se[r0 + i + 3];
        float4 vA = *(const float4*)(g_qt + (size_t)qA * HD + c4 * 4);
        float4 vB = *(const float4*)(g_qt + (size_t)(qA + 1) * HD + c4 * 4);
        float4 vC = *(const float4*)(g_qt + (size_t)(qA + 2) * HD + c4 * 4);
        float4 vD = *(const float4*)(g_qt + (size_t)(qA + 3) * HD + c4 * 4);
        a0.x = fmaf(sA, vA.x, a0.x); a0.y = fmaf(sA, vA.y, a0.y);
        a0.z = fmaf(sA, vA.z, a0.z); a0.w = fmaf(sA, vA.w, a0.w);
        a1.x = fmaf(sB, vB.x, a1.x); a1.y = fmaf(sB, vB.y, a1.y);
        a1.z = fmaf(sB, vB.z, a1.z); a1.w = fmaf(sB, vB.w, a1.w);
        a2.x = fmaf(sC, vC.x, a2.x); a2.y = fmaf(sC, vC.y, a2.y);
        a2.z = fmaf(sC, vC.z, a2.z); a2.w = fmaf(sC, vC.w, a2.w);
        a3.x = fmaf(sD, vD.x, a3.x); a3.y = fmaf(sD, vD.y, a3.y);
        a3.z = fmaf(sD, vD.z, a3.z); a3.w = fmaf(sD, vD.w, a3.w);
    }
    int lc = (tid & 63) * 4;
    atomicAdd(&sz[lc + 0], a0.x + a1.x + a2.x + a3.x);
    atomicAdd(&sz[lc + 1], a0.y + a1.y + a2.y + a3.y);
    atomicAdd(&sz[lc + 2], a0.z + a1.z + a2.z + a3.z);
    atomicAdd(&sz[lc + 3], a0.w + a1.w + a2.w + a3.w);
    __syncthreads();
    atomicAdd(&g_z[cbase * 4 + tid], sz[tid]);
}

// ---------------------------------------------------------------------------
__global__ void final_kernel(const float* __restrict__ cls_w,
                             const float* __restrict__ cls_b,
                             float* __restrict__ out) {
    __shared__ float red[16];
    int t = threadIdx.x;
    float p = g_z[t] * cls_w[t] + g_z[t + 256] * cls_w[t + 256];
#pragma unroll
    for (int o = 16; o > 0; o >>= 1) p += __shfl_xor_sync(0xffffffffu, p, o);
    int lane = t & 31, w = t >> 5;
    if (lane == 0) red[w] = p;
    __syncthreads();
    if (w == 0) {
        float s = (lane < 8) ? red[lane] : 0.f;
#pragma unroll
        for (int o = 4; o > 0; o >>= 1) s += __shfl_xor_sync(0xffffffffu, s, o);
        if (lane == 0) out[0] = s / g_Z + cls_b[0];
    }
}

// ---------------------------------------------------------------------------
extern "C" void kernel_launch(void* const* d_in, const int* in_sizes, int n_in,
                              void* d_out, int out_size) {
    const float* query = (const float*)d_in[0];
    const float* key_x = (const float*)d_in[1];
    const float* wq_w  = (const float*)d_in[2];
    const float* wq_b  = (const float*)d_in[3];
    const float* wk_w  = (const float*)d_in[4];
    const float* wk_b  = (const float*)d_in[5];
    const float* wa_w  = (const float*)d_in[6];
    const float* wa_b  = (const float*)d_in[7];
    const float* cls_w = (const float*)d_in[8];
    const float* cls_b = (const float*)d_in[9];
    float* out = (float*)d_out;

    cudaFuncSetAttribute(gemm_tc_kernel,
                         cudaFuncAttributeMaxDynamicSharedMemorySize, GEMM_SMEM);

    init_kernel<<<1, 512>>>();
    wconv_kernel<<<2 * W4 / 256, 256>>>(wq_w, wk_w);

    int nblocks = NQ / 64 + (NK + 63) / 64;    // 256 + 124 = 380
    gemm_tc_kernel<<<nblocks, 512, GEMM_SMEM>>>(query, wq_b, key_x, wk_b);

    v_accum_kernel<<<dim3((NK + 31) / 32, 2), 256>>>(wa_w);
    a1_kernel<<<NQ / 32, 256>>>(wa_b);
    select_kernel<<<1, 1024>>>();
    e_accum_kernel<<<dim3(NQ / 32, 2), 256>>>(out);
    final_kernel<<<1, 256>>>(cls_w, cls_b, out);
}